// round 15
// baseline (speedup 1.0000x reference)
#include <cuda_runtime.h>
#include <cstdint>

#define B_  4
#define T_  12
#define N_  307
#define NP1 308
#define DE_ 1024
#define H_  16
#define LK_ 153
#define K1_ 154
#define TK_ 1848
#define BT_ 48
#define SORT_SZ 512
#define NCHUNK_ 44                          // src-row stripes per (b,h)
#define RPB_ 7                              // rows per bias block (308/44)
#define NBIAS_BLOCKS (B_ * H_ * NCHUNK_)    // 2816
#define XG_ROWS (BT_ * LK_)                 // 7344
#define NXG_BLOCKS (XG_ROWS / 4)            // 1836

__device__ int g_idsk[B_ * TK_];        // [b][t*K1+k] = src index (0 or id+1)
__device__ __align__(16) int g_slot[B_][NP1][T_];   // out row or -1 (fully rewritten)

// ---------------------------------------------------------------------------
// Bitonic argsort per (b,t); emits mask, g_idsk, and inverse slot table.
// Stages with j<32 are warp-local (pair (i, i^j) and its writer stay inside
// the same 32-aligned window), so they need only __syncwarp. Block-wide sync
// is required iff the current OR previous stage had j>=32.
// ---------------------------------------------------------------------------
__global__ void sort_kernel(const float* __restrict__ noise,
                            float* __restrict__ mask_out) {
    __shared__ unsigned long long s[SORT_SZ];
    const int tid = threadIdx.x;
    const int bt  = blockIdx.x;
    const int b   = bt / T_;
    const int t   = bt - b * T_;

    float v = (tid < N_) ? noise[bt * N_ + tid] : __int_as_float(0x7F800000);
    unsigned u = __float_as_uint(v);
    u = (u & 0x80000000u) ? ~u : (u | 0x80000000u);
    s[tid] = ((unsigned long long)u << 32) | (unsigned)tid;

    int prevj = 0;
    for (int k = 2; k <= SORT_SZ; k <<= 1) {
        for (int j = k >> 1; j > 0; j >>= 1) {
            if (j >= 32 || prevj >= 32) __syncthreads();
            else                        __syncwarp();
            int ixj = tid ^ j;
            if (ixj > tid) {
                unsigned long long a = s[tid], c = s[ixj];
                bool up = ((tid & k) == 0);
                if ((a > c) == up) { s[tid] = c; s[ixj] = a; }
            }
            prevj = j;
        }
    }
    __syncwarp();   // last stage (j=1) wrote within-warp; s[tid] now stable

    if (tid < N_) {
        int idx = (int)(s[tid] & 0xFFFFFFFFull);
        mask_out[bt * N_ + idx] = (tid >= LK_) ? 1.0f : 0.0f;
        if (tid < LK_) {
            g_idsk[bt * K1_ + 1 + tid] = idx + 1;
            g_slot[b][idx + 1][t] = t * K1_ + 1 + tid;   // kept
        } else {
            g_slot[b][idx + 1][t] = -1;                  // dropped
        }
    }
    if (tid == 0) {
        g_idsk[bt * K1_] = 0;
        g_slot[b][0][t] = t * K1_;                       // cls row always kept
    }
}

// ---------------------------------------------------------------------------
// Fat kernel: bias (dedup-gather, double-buffered) + x_masked copy tail.
// Bias block = (b,h,chunk): for each of 7 striped src rows, gather the 1848
// permuted columns ONCE into registers, replay to all duplicate output rows
// with streaming (.cs) stores — the one-shot write stream must not evict the
// L2-resident bias table / maps.
// ---------------------------------------------------------------------------
__global__ __launch_bounds__(256)
void fat_kernel(const float* __restrict__ bias,
                const float* __restrict__ w,
                float* __restrict__ out_bias,
                const float4* __restrict__ x,
                float4* __restrict__ xm) {
    const int tid = threadIdx.x;

    if (blockIdx.x >= NBIAS_BLOCKS) {
        // ---- x_masked gather: 4 rows per block, MLP=4 ----
        const int r0 = (blockIdx.x - NBIAS_BLOCKS) * 4;
        float4 v[4]; float4* dst[4];
        #pragma unroll
        for (int j = 0; j < 4; j++) {
            const int row = r0 + j;
            const int bt  = row / LK_;
            const int k   = row - bt * LK_;
            const int id  = __ldg(g_idsk + bt * K1_ + 1 + k) - 1;
            v[j]   = __ldcs(x + ((size_t)bt * N_ + id) * (DE_ / 4) + tid);
            dst[j] = xm + (size_t)row * (DE_ / 4) + tid;
        }
        #pragma unroll
        for (int j = 0; j < 4; j++) __stcs(dst[j], v[j]);
        return;
    }

    __shared__ int   s_map[TK_];
    __shared__ __align__(16) float s_src[2][NP1];
    __shared__ __align__(16) int   s_list[2][T_];

    const int chunk = blockIdx.x % NCHUNK_;
    const int bh    = blockIdx.x / NCHUNK_;
    const int h     = bh & (H_ - 1);
    const int b     = bh >> 4;

    const int*    __restrict__ rmap = g_idsk + b * TK_;
    const float4* __restrict__ b4   = (const float4*)(bias + (size_t)bh * NP1 * NP1);
    const float wh = w[h];

    for (int j = tid; j < TK_; j += 256) s_map[j] = rmap[j];

    // Prefetch first striped row (row data + its 12 slots)
    if (tid < NP1 / 4) ((float4*)s_src[0])[tid] = b4[chunk * (NP1 / 4) + tid];
    if (tid < T_)      s_list[0][tid] = g_slot[b][chunk][tid];
    __syncthreads();

    // Column indices + zero-column add (map-invariant across src rows)
    const int4 ca = ((const int4*)s_map)[tid];
    const bool hasb = (tid + 256) < (TK_ / 4);
    int4 cb = make_int4(0, 0, 0, 0);
    if (hasb) cb = ((const int4*)s_map)[tid + 256];
    const float ma_x = (ca.x == 0) ? wh : 0.0f, ma_y = (ca.y == 0) ? wh : 0.0f;
    const float ma_z = (ca.z == 0) ? wh : 0.0f, ma_w = (ca.w == 0) ? wh : 0.0f;
    const float mb_x = (cb.x == 0) ? wh : 0.0f, mb_y = (cb.y == 0) ? wh : 0.0f;
    const float mb_z = (cb.z == 0) ? wh : 0.0f, mb_w = (cb.w == 0) ? wh : 0.0f;

    int buf = 0;
    #pragma unroll
    for (int it = 0; it < RPB_; it++) {
        const int r = chunk + it * NCHUNK_;

        // Issue next row's prefetch (latency hidden under this row's stores)
        float4 pre; int slotn = 0;
        const bool hasnext = (it + 1 < RPB_);
        if (hasnext) {
            const int rn = r + NCHUNK_;
            if (tid < NP1 / 4) pre = b4[rn * (NP1 / 4) + tid];
            if (tid < T_)      slotn = g_slot[b][rn][tid];
        }

        // Gather once into registers (wh applied iff r==0 OR c==0, once)
        const bool  r0 = (r == 0);
        const float* sr = s_src[buf];
        float4 v0, v1;
        v0.x = sr[ca.x] + (r0 ? wh : ma_x);
        v0.y = sr[ca.y] + (r0 ? wh : ma_y);
        v0.z = sr[ca.z] + (r0 ? wh : ma_z);
        v0.w = sr[ca.w] + (r0 ? wh : ma_w);
        if (hasb) {
            v1.x = sr[cb.x] + (r0 ? wh : mb_x);
            v1.y = sr[cb.y] + (r0 ? wh : mb_y);
            v1.z = sr[cb.z] + (r0 ? wh : mb_z);
            v1.w = sr[cb.w] + (r0 ? wh : mb_w);
        }

        // Replay to every duplicate output row (streaming stores)
        #pragma unroll
        for (int t = 0; t < T_; t++) {
            const int row = s_list[buf][t];
            if (row < 0) continue;
            float4* orow = (float4*)(out_bias + ((size_t)bh * TK_ + row) * TK_);
            __stcs(orow + tid, v0);
            if (hasb) __stcs(orow + tid + 256, v1);
        }

        // Commit prefetch into the other buffer
        if (hasnext) {
            if (tid < NP1 / 4) ((float4*)s_src[buf ^ 1])[tid] = pre;
            if (tid < T_)      s_list[buf ^ 1][tid] = slotn;
        }
        __syncthreads();
        buf ^= 1;
    }
}

// ---------------------------------------------------------------------------
extern "C" void kernel_launch(void* const* d_in, const int* in_sizes, int n_in,
                              void* d_out, int out_size) {
    const float* x     = (const float*)d_in[0];  // (4,12,307,1024)
    const float* bias  = (const float*)d_in[1];  // (4,16,308,308)
    const float* w     = (const float*)d_in[2];  // (1,16)
    const float* noise = (const float*)d_in[3];  // (4,12,307)

    float* out = (float*)d_out;
    const size_t xm_elems   = (size_t)BT_ * LK_ * DE_;
    const size_t mask_elems = (size_t)BT_ * N_;
    float* out_xm   = out;
    float* out_mask = out + xm_elems;
    float* out_bias = out + xm_elems + mask_elems;

    sort_kernel<<<BT_, SORT_SZ>>>(noise, out_mask);
    fat_kernel<<<NBIAS_BLOCKS + NXG_BLOCKS, 256>>>(
        bias, w, out_bias, (const float4*)x, (float4*)out_xm);
}

// round 16
// speedup vs baseline: 1.0240x; 1.0240x over previous
#include <cuda_runtime.h>
#include <cstdint>

#define B_  4
#define T_  12
#define N_  307
#define NP1 308
#define DE_ 1024
#define H_  16
#define LK_ 153
#define K1_ 154
#define TK_ 1848
#define BT_ 48
#define SORT_SZ 512
#define NCHUNK_ 44                          // src-row stripes per (b,h)
#define RPB_ 7                              // rows per bias block (308/44)
#define NBIAS_BLOCKS (B_ * H_ * NCHUNK_)    // 2816
#define XG_ROWS (BT_ * LK_)                 // 7344
#define NXG_BLOCKS (XG_ROWS / 4)            // 1836

__device__ int g_idsk[B_ * TK_];        // [b][t*K1+k] = src index (0 or id+1)
__device__ __align__(16) int g_slot[B_][NP1][T_];   // out row or -1 (fully rewritten)

// ---------------------------------------------------------------------------
// Bitonic argsort per (b,t); emits mask, g_idsk, and inverse slot table.
// Triggers the dependent fat_kernel launch immediately (PDL): fat's blocks
// get scheduled and park at cudaGridDependencySynchronize() while we sort.
// Stages with j<32 are warp-local -> __syncwarp; block sync iff cur/prev j>=32.
// ---------------------------------------------------------------------------
__global__ void sort_kernel(const float* __restrict__ noise,
                            float* __restrict__ mask_out) {
    cudaTriggerProgrammaticLaunchCompletion();   // let fat_kernel ramp up now

    __shared__ unsigned long long s[SORT_SZ];
    const int tid = threadIdx.x;
    const int bt  = blockIdx.x;
    const int b   = bt / T_;
    const int t   = bt - b * T_;

    float v = (tid < N_) ? noise[bt * N_ + tid] : __int_as_float(0x7F800000);
    unsigned u = __float_as_uint(v);
    u = (u & 0x80000000u) ? ~u : (u | 0x80000000u);
    s[tid] = ((unsigned long long)u << 32) | (unsigned)tid;

    int prevj = 0;
    for (int k = 2; k <= SORT_SZ; k <<= 1) {
        for (int j = k >> 1; j > 0; j >>= 1) {
            if (j >= 32 || prevj >= 32) __syncthreads();
            else                        __syncwarp();
            int ixj = tid ^ j;
            if (ixj > tid) {
                unsigned long long a = s[tid], c = s[ixj];
                bool up = ((tid & k) == 0);
                if ((a > c) == up) { s[tid] = c; s[ixj] = a; }
            }
            prevj = j;
        }
    }
    __syncwarp();   // last stage (j=1) wrote within-warp; s[tid] now stable

    if (tid < N_) {
        int idx = (int)(s[tid] & 0xFFFFFFFFull);
        mask_out[bt * N_ + idx] = (tid >= LK_) ? 1.0f : 0.0f;
        if (tid < LK_) {
            g_idsk[bt * K1_ + 1 + tid] = idx + 1;
            g_slot[b][idx + 1][t] = t * K1_ + 1 + tid;   // kept
        } else {
            g_slot[b][idx + 1][t] = -1;                  // dropped
        }
    }
    if (tid == 0) {
        g_idsk[bt * K1_] = 0;
        g_slot[b][0][t] = t * K1_;                       // cls row always kept
    }
}

// ---------------------------------------------------------------------------
// Fat kernel: bias (dedup-gather, double-buffered) + x_masked copy tail.
// Launched with PDL: blocks start during sort_kernel and wait at
// cudaGridDependencySynchronize() — all of sort's global writes (g_idsk,
// g_slot, mask) are visible after the sync. Streaming (.cs) stores keep the
// one-shot 874 MB write stream from evicting the L2-resident bias/maps.
// ---------------------------------------------------------------------------
__global__ __launch_bounds__(256)
void fat_kernel(const float* __restrict__ bias,
                const float* __restrict__ w,
                float* __restrict__ out_bias,
                const float4* __restrict__ x,
                float4* __restrict__ xm) {
    const int tid = threadIdx.x;

    cudaGridDependencySynchronize();   // sort's writes now visible

    if (blockIdx.x >= NBIAS_BLOCKS) {
        // ---- x_masked gather: 4 rows per block, MLP=4 ----
        const int r0 = (blockIdx.x - NBIAS_BLOCKS) * 4;
        float4 v[4]; float4* dst[4];
        #pragma unroll
        for (int j = 0; j < 4; j++) {
            const int row = r0 + j;
            const int bt  = row / LK_;
            const int k   = row - bt * LK_;
            const int id  = __ldg(g_idsk + bt * K1_ + 1 + k) - 1;
            v[j]   = __ldcs(x + ((size_t)bt * N_ + id) * (DE_ / 4) + tid);
            dst[j] = xm + (size_t)row * (DE_ / 4) + tid;
        }
        #pragma unroll
        for (int j = 0; j < 4; j++) __stcs(dst[j], v[j]);
        return;
    }

    __shared__ int   s_map[TK_];
    __shared__ __align__(16) float s_src[2][NP1];
    __shared__ __align__(16) int   s_list[2][T_];

    const int chunk = blockIdx.x % NCHUNK_;
    const int bh    = blockIdx.x / NCHUNK_;
    const int h     = bh & (H_ - 1);
    const int b     = bh >> 4;

    const int*    __restrict__ rmap = g_idsk + b * TK_;
    const float4* __restrict__ b4   = (const float4*)(bias + (size_t)bh * NP1 * NP1);
    const float wh = w[h];

    for (int j = tid; j < TK_; j += 256) s_map[j] = rmap[j];

    // Prefetch first striped row (row data + its 12 slots)
    if (tid < NP1 / 4) ((float4*)s_src[0])[tid] = b4[chunk * (NP1 / 4) + tid];
    if (tid < T_)      s_list[0][tid] = g_slot[b][chunk][tid];
    __syncthreads();

    // Column indices + zero-column add (map-invariant across src rows)
    const int4 ca = ((const int4*)s_map)[tid];
    const bool hasb = (tid + 256) < (TK_ / 4);
    int4 cb = make_int4(0, 0, 0, 0);
    if (hasb) cb = ((const int4*)s_map)[tid + 256];
    const float ma_x = (ca.x == 0) ? wh : 0.0f, ma_y = (ca.y == 0) ? wh : 0.0f;
    const float ma_z = (ca.z == 0) ? wh : 0.0f, ma_w = (ca.w == 0) ? wh : 0.0f;
    const float mb_x = (cb.x == 0) ? wh : 0.0f, mb_y = (cb.y == 0) ? wh : 0.0f;
    const float mb_z = (cb.z == 0) ? wh : 0.0f, mb_w = (cb.w == 0) ? wh : 0.0f;

    int buf = 0;
    #pragma unroll
    for (int it = 0; it < RPB_; it++) {
        const int r = chunk + it * NCHUNK_;

        // Issue next row's prefetch (latency hidden under this row's stores)
        float4 pre; int slotn = 0;
        const bool hasnext = (it + 1 < RPB_);
        if (hasnext) {
            const int rn = r + NCHUNK_;
            if (tid < NP1 / 4) pre = b4[rn * (NP1 / 4) + tid];
            if (tid < T_)      slotn = g_slot[b][rn][tid];
        }

        // Gather once into registers (wh applied iff r==0 OR c==0, once)
        const bool  r0 = (r == 0);
        const float* sr = s_src[buf];
        float4 v0, v1;
        v0.x = sr[ca.x] + (r0 ? wh : ma_x);
        v0.y = sr[ca.y] + (r0 ? wh : ma_y);
        v0.z = sr[ca.z] + (r0 ? wh : ma_z);
        v0.w = sr[ca.w] + (r0 ? wh : ma_w);
        if (hasb) {
            v1.x = sr[cb.x] + (r0 ? wh : mb_x);
            v1.y = sr[cb.y] + (r0 ? wh : mb_y);
            v1.z = sr[cb.z] + (r0 ? wh : mb_z);
            v1.w = sr[cb.w] + (r0 ? wh : mb_w);
        }

        // Replay to every duplicate output row (streaming stores)
        #pragma unroll
        for (int t = 0; t < T_; t++) {
            const int row = s_list[buf][t];
            if (row < 0) continue;
            float4* orow = (float4*)(out_bias + ((size_t)bh * TK_ + row) * TK_);
            __stcs(orow + tid, v0);
            if (hasb) __stcs(orow + tid + 256, v1);
        }

        // Commit prefetch into the other buffer
        if (hasnext) {
            if (tid < NP1 / 4) ((float4*)s_src[buf ^ 1])[tid] = pre;
            if (tid < T_)      s_list[buf ^ 1][tid] = slotn;
        }
        __syncthreads();
        buf ^= 1;
    }
}

// ---------------------------------------------------------------------------
extern "C" void kernel_launch(void* const* d_in, const int* in_sizes, int n_in,
                              void* d_out, int out_size) {
    const float* x     = (const float*)d_in[0];  // (4,12,307,1024)
    const float* bias  = (const float*)d_in[1];  // (4,16,308,308)
    const float* w     = (const float*)d_in[2];  // (1,16)
    const float* noise = (const float*)d_in[3];  // (4,12,307)

    float* out = (float*)d_out;
    const size_t xm_elems   = (size_t)BT_ * LK_ * DE_;
    const size_t mask_elems = (size_t)BT_ * N_;
    float* out_xm   = out;
    float* out_mask = out + xm_elems;
    float* out_bias = out + xm_elems + mask_elems;

    sort_kernel<<<BT_, SORT_SZ>>>(noise, out_mask);

    // Dependent launch with programmatic stream serialization: fat_kernel's
    // blocks may be scheduled while sort_kernel is still running; correctness
    // is enforced by cudaGridDependencySynchronize() inside the kernel.
    cudaLaunchConfig_t cfg = {};
    cfg.gridDim  = dim3(NBIAS_BLOCKS + NXG_BLOCKS, 1, 1);
    cfg.blockDim = dim3(256, 1, 1);
    cfg.dynamicSmemBytes = 0;
    cudaLaunchAttribute attr[1];
    attr[0].id = cudaLaunchAttributeProgrammaticStreamSerialization;
    attr[0].val.programmaticStreamSerializationAllowed = 1;
    cfg.attrs = attr;
    cfg.numAttrs = 1;
    cudaLaunchKernelEx(&cfg, fat_kernel,
                       bias, w, out_bias, (const float4*)x, (float4*)out_xm);
}

// round 17
// speedup vs baseline: 1.0248x; 1.0008x over previous
#include <cuda_runtime.h>
#include <cstdint>

#define B_  4
#define T_  12
#define N_  307
#define NP1 308
#define DE_ 1024
#define H_  16
#define LK_ 153
#define K1_ 154
#define TK_ 1848
#define BT_ 48
#define SORT_SZ 512
#define NCHUNK_ 44                          // src-row stripes per (b,h)
#define RPB_ 7                              // rows per bias block (308/44)
#define NBIAS_BLOCKS (B_ * H_ * NCHUNK_)    // 2816
#define XG_ROWS (BT_ * LK_)                 // 7344
#define NXG_BLOCKS (XG_ROWS / 4)            // 1836

__device__ int g_idsk[B_ * TK_];        // [b][t*K1+k] = src index (0 or id+1)
__device__ __align__(16) int g_slot[B_][NP1][T_];   // out row or -1 (fully rewritten)

// ---------------------------------------------------------------------------
// Bitonic argsort per (b,t); emits mask, g_idsk, and inverse slot table.
// Triggers the dependent fat_kernel launch immediately (PDL): fat's blocks
// get scheduled, issue their sort-independent bias prefetches, and park at
// cudaGridDependencySynchronize() while we sort.
// Stages with j<32 are warp-local -> __syncwarp; block sync iff cur/prev j>=32.
// ---------------------------------------------------------------------------
__global__ void sort_kernel(const float* __restrict__ noise,
                            float* __restrict__ mask_out) {
    cudaTriggerProgrammaticLaunchCompletion();   // let fat_kernel ramp up now

    __shared__ unsigned long long s[SORT_SZ];
    const int tid = threadIdx.x;
    const int bt  = blockIdx.x;
    const int b   = bt / T_;
    const int t   = bt - b * T_;

    float v = (tid < N_) ? noise[bt * N_ + tid] : __int_as_float(0x7F800000);
    unsigned u = __float_as_uint(v);
    u = (u & 0x80000000u) ? ~u : (u | 0x80000000u);
    s[tid] = ((unsigned long long)u << 32) | (unsigned)tid;

    int prevj = 0;
    for (int k = 2; k <= SORT_SZ; k <<= 1) {
        for (int j = k >> 1; j > 0; j >>= 1) {
            if (j >= 32 || prevj >= 32) __syncthreads();
            else                        __syncwarp();
            int ixj = tid ^ j;
            if (ixj > tid) {
                unsigned long long a = s[tid], c = s[ixj];
                bool up = ((tid & k) == 0);
                if ((a > c) == up) { s[tid] = c; s[ixj] = a; }
            }
            prevj = j;
        }
    }
    __syncwarp();   // last stage (j=1) wrote within-warp; s[tid] now stable

    if (tid < N_) {
        int idx = (int)(s[tid] & 0xFFFFFFFFull);
        mask_out[bt * N_ + idx] = (tid >= LK_) ? 1.0f : 0.0f;
        if (tid < LK_) {
            g_idsk[bt * K1_ + 1 + tid] = idx + 1;
            g_slot[b][idx + 1][t] = t * K1_ + 1 + tid;   // kept
        } else {
            g_slot[b][idx + 1][t] = -1;                  // dropped
        }
    }
    if (tid == 0) {
        g_idsk[bt * K1_] = 0;
        g_slot[b][0][t] = t * K1_;                       // cls row always kept
    }
}

// ---------------------------------------------------------------------------
// Fat kernel: bias (dedup-gather, double-buffered) + x_masked copy tail.
// Launched with PDL. Bias blocks issue their first source-row load (depends
// only on blockIdx + bias input) BEFORE the grid sync, so the read latency
// overlaps sort's tail; all g_idsk/g_slot reads come after the sync.
// Streaming (.cs) stores keep the one-shot 874 MB write stream from evicting
// the L2-resident bias/maps.
// ---------------------------------------------------------------------------
__global__ __launch_bounds__(256)
void fat_kernel(const float* __restrict__ bias,
                const float* __restrict__ w,
                float* __restrict__ out_bias,
                const float4* __restrict__ x,
                float4* __restrict__ xm) {
    const int tid = threadIdx.x;

    if (blockIdx.x >= NBIAS_BLOCKS) {
        // ---- x_masked gather: 4 rows per block, MLP=4 ----
        cudaGridDependencySynchronize();   // needs g_idsk
        const int r0 = (blockIdx.x - NBIAS_BLOCKS) * 4;
        float4 v[4]; float4* dst[4];
        #pragma unroll
        for (int j = 0; j < 4; j++) {
            const int row = r0 + j;
            const int bt  = row / LK_;
            const int k   = row - bt * LK_;
            const int id  = __ldg(g_idsk + bt * K1_ + 1 + k) - 1;
            v[j]   = __ldcs(x + ((size_t)bt * N_ + id) * (DE_ / 4) + tid);
            dst[j] = xm + (size_t)row * (DE_ / 4) + tid;
        }
        #pragma unroll
        for (int j = 0; j < 4; j++) __stcs(dst[j], v[j]);
        return;
    }

    __shared__ int   s_map[TK_];
    __shared__ __align__(16) float s_src[2][NP1];
    __shared__ __align__(16) int   s_list[2][T_];

    const int chunk = blockIdx.x % NCHUNK_;
    const int bh    = blockIdx.x / NCHUNK_;
    const int h     = bh & (H_ - 1);
    const int b     = bh >> 4;

    const float4* __restrict__ b4 = (const float4*)(bias + (size_t)bh * NP1 * NP1);
    const float wh = w[h];

    // Sort-independent prefetch of the first striped source row: issue the
    // global load BEFORE the grid sync so it flies during sort's tail.
    float4 first_row;
    if (tid < NP1 / 4) first_row = b4[chunk * (NP1 / 4) + tid];

    cudaGridDependencySynchronize();   // sort's writes now visible

    const int* __restrict__ rmap = g_idsk + b * TK_;
    for (int j = tid; j < TK_; j += 256) s_map[j] = rmap[j];

    if (tid < NP1 / 4) ((float4*)s_src[0])[tid] = first_row;
    if (tid < T_)      s_list[0][tid] = g_slot[b][chunk][tid];
    __syncthreads();

    // Column indices + zero-column add (map-invariant across src rows)
    const int4 ca = ((const int4*)s_map)[tid];
    const bool hasb = (tid + 256) < (TK_ / 4);
    int4 cb = make_int4(0, 0, 0, 0);
    if (hasb) cb = ((const int4*)s_map)[tid + 256];
    const float ma_x = (ca.x == 0) ? wh : 0.0f, ma_y = (ca.y == 0) ? wh : 0.0f;
    const float ma_z = (ca.z == 0) ? wh : 0.0f, ma_w = (ca.w == 0) ? wh : 0.0f;
    const float mb_x = (cb.x == 0) ? wh : 0.0f, mb_y = (cb.y == 0) ? wh : 0.0f;
    const float mb_z = (cb.z == 0) ? wh : 0.0f, mb_w = (cb.w == 0) ? wh : 0.0f;

    int buf = 0;
    #pragma unroll
    for (int it = 0; it < RPB_; it++) {
        const int r = chunk + it * NCHUNK_;

        // Issue next row's prefetch (latency hidden under this row's stores)
        float4 pre; int slotn = 0;
        const bool hasnext = (it + 1 < RPB_);
        if (hasnext) {
            const int rn = r + NCHUNK_;
            if (tid < NP1 / 4) pre = b4[rn * (NP1 / 4) + tid];
            if (tid < T_)      slotn = g_slot[b][rn][tid];
        }

        // Gather once into registers (wh applied iff r==0 OR c==0, once)
        const bool  r0 = (r == 0);
        const float* sr = s_src[buf];
        float4 v0, v1;
        v0.x = sr[ca.x] + (r0 ? wh : ma_x);
        v0.y = sr[ca.y] + (r0 ? wh : ma_y);
        v0.z = sr[ca.z] + (r0 ? wh : ma_z);
        v0.w = sr[ca.w] + (r0 ? wh : ma_w);
        if (hasb) {
            v1.x = sr[cb.x] + (r0 ? wh : mb_x);
            v1.y = sr[cb.y] + (r0 ? wh : mb_y);
            v1.z = sr[cb.z] + (r0 ? wh : mb_z);
            v1.w = sr[cb.w] + (r0 ? wh : mb_w);
        }

        // Replay to every duplicate output row (streaming stores)
        #pragma unroll
        for (int t = 0; t < T_; t++) {
            const int row = s_list[buf][t];
            if (row < 0) continue;
            float4* orow = (float4*)(out_bias + ((size_t)bh * TK_ + row) * TK_);
            __stcs(orow + tid, v0);
            if (hasb) __stcs(orow + tid + 256, v1);
        }

        // Commit prefetch into the other buffer
        if (hasnext) {
            if (tid < NP1 / 4) ((float4*)s_src[buf ^ 1])[tid] = pre;
            if (tid < T_)      s_list[buf ^ 1][tid] = slotn;
        }
        __syncthreads();
        buf ^= 1;
    }
}

// ---------------------------------------------------------------------------
extern "C" void kernel_launch(void* const* d_in, const int* in_sizes, int n_in,
                              void* d_out, int out_size) {
    const float* x     = (const float*)d_in[0];  // (4,12,307,1024)
    const float* bias  = (const float*)d_in[1];  // (4,16,308,308)
    const float* w     = (const float*)d_in[2];  // (1,16)
    const float* noise = (const float*)d_in[3];  // (4,12,307)

    float* out = (float*)d_out;
    const size_t xm_elems   = (size_t)BT_ * LK_ * DE_;
    const size_t mask_elems = (size_t)BT_ * N_;
    float* out_xm   = out;
    float* out_mask = out + xm_elems;
    float* out_bias = out + xm_elems + mask_elems;

    sort_kernel<<<BT_, SORT_SZ>>>(noise, out_mask);

    // Dependent launch with programmatic stream serialization: fat_kernel's
    // blocks may be scheduled while sort_kernel is still running; correctness
    // is enforced by cudaGridDependencySynchronize() inside the kernel.
    cudaLaunchConfig_t cfg = {};
    cfg.gridDim  = dim3(NBIAS_BLOCKS + NXG_BLOCKS, 1, 1);
    cfg.blockDim = dim3(256, 1, 1);
    cfg.dynamicSmemBytes = 0;
    cudaLaunchAttribute attr[1];
    attr[0].id = cudaLaunchAttributeProgrammaticStreamSerialization;
    attr[0].val.programmaticStreamSerializationAllowed = 1;
    cfg.attrs = attr;
    cfg.numAttrs = 1;
    cudaLaunchKernelEx(&cfg, fat_kernel,
                       bias, w, out_bias, (const float4*)x, (float4*)out_xm);
}